// round 5
// baseline (speedup 1.0000x reference)
#include <cuda_runtime.h>

// ---------------- problem constants ----------------
#define NTHREAD 256
#define ROWS 16              // rows per CTA = 4 teams x 4 rows
static constexpr int Bb = 2048, Tt = 256, Ff = 64;
static constexpr int K0 = 128, N0 = 256;   // layer0: [x(64)|h0(64)] -> 4*64
static constexpr int K1 = 96,  N1 = 128;   // layer1: [h0(64)|h1(32)] -> 4*32
static constexpr int K2 = 48,  N2 = 64;    // layer2: [h1(32)|h2(16)] -> 4*16

// ---------------- shared memory layout (float offsets) ----------------
static constexpr int OFF_W0 = 0;                     // 2 halves x 128k x 128 cols
static constexpr int OFF_W1 = OFF_W0 + K0 * N0;      // 32768 (2 halves x 96 x 64)
static constexpr int OFF_W2 = OFF_W1 + K1 * N1;      // 45056 (identity layout)
static constexpr int OFF_B0 = OFF_W2 + K2 * N2;      // 48128
static constexpr int OFF_B1 = OFF_B0 + N0;           // 48384
static constexpr int OFF_B2 = OFF_B1 + N1;           // 48512
static constexpr int OFF_WD = OFF_B2 + N2;           // 48576
static constexpr int OFF_V0 = OFF_WD + 16;           // 48592
static constexpr int OFF_V1 = OFF_V0 + ROWS * K0;    // 50640
static constexpr int OFF_V2 = OFF_V1 + ROWS * K1;    // 52176
static constexpr int OFF_SC = OFF_V2 + ROWS * K2;    // 52944 (8B aligned: even)
static constexpr int SMEM_FLOATS = OFF_SC + 4 * 384; // + 4 teams * (128 ull + 128 f)
static constexpr size_t SMEM_BYTES = (size_t)SMEM_FLOATS * sizeof(float); // 217920 B

typedef unsigned long long ull;

// ---------------- packed f32x2 helpers ----------------
__device__ __forceinline__ void fma2(ull& acc, ull a, ull b) {
    asm("fma.rn.f32x2 %0, %1, %2, %0;" : "+l"(acc) : "l"(a), "l"(b));
}
__device__ __forceinline__ ull dup2(float v) {
    ull u; asm("mov.b64 %0, {%1, %1};" : "=l"(u) : "f"(v)); return u;
}
__device__ __forceinline__ ull pk2(float x, float y) {
    ull u; asm("mov.b64 %0, {%1, %2};" : "=l"(u) : "f"(x), "f"(y)); return u;
}
__device__ __forceinline__ float2 unpk(ull u) {
    float2 r; asm("mov.b64 {%0, %1}, %2;" : "=f"(r.x), "=f"(r.y) : "l"(u)); return r;
}
__device__ __forceinline__ float sigf(float x) {
    return __fdividef(1.0f, 1.0f + __expf(-x));
}
__device__ __forceinline__ float tanhf_(float x) {
    float e = __expf(-2.0f * x);
    return __fdividef(2.0f, 1.0f + e) - 1.0f;
}
__device__ __forceinline__ void team_bar(int id) {
    asm volatile("bar.sync %0, 64;" :: "r"(id) : "memory");
}

__global__ void __launch_bounds__(NTHREAD, 1)
stacked_lstm_kernel(const float* __restrict__ x,
                    const float* __restrict__ W0, const float* __restrict__ U0, const float* __restrict__ b0,
                    const float* __restrict__ W1, const float* __restrict__ U1, const float* __restrict__ b1,
                    const float* __restrict__ W2, const float* __restrict__ U2, const float* __restrict__ b2,
                    const float* __restrict__ Wd, const float* __restrict__ bd,
                    float* __restrict__ out) {
    extern __shared__ float S[];
    const int tid = threadIdx.x, lane = tid & 31, warp = tid >> 5;
    const int team = warp >> 1, half = warp & 1;
    const int barid = team + 1;

    // ---- stage weights into smem, N-split permuted ----
    // L0: half 0 holds gates (i,g), half 1 holds (f,o); within a half, lane l's
    // LDS.128 at [k*128 + l*4] = { gA(2l), gA(2l+1), gB(2l), gB(2l+1) }.
    for (int idx = tid; idx < K0 * N0; idx += NTHREAD) {
        int k = idx >> 8, j = idx & (N0 - 1);
        float v = (k < 64) ? W0[k * N0 + j] : U0[(k - 64) * N0 + j];
        int g = j >> 6, h = j & 63, hf = g & 1, gg = g >> 1, l = h >> 1, e = h & 1;
        S[OFF_W0 + hf * 16384 + k * 128 + l * 4 + gg * 2 + e] = v;
    }
    // L1: lane l's LDS.64 at [k*64 + h*2] = { gA(h), gB(h) }, h = lane
    for (int idx = tid; idx < K1 * N1; idx += NTHREAD) {
        int k = idx >> 7, j = idx & (N1 - 1);
        float v = (k < 64) ? W1[k * N1 + j] : U1[(k - 64) * N1 + j];
        int g = j >> 5, h = j & 31, hf = g & 1, gg = g >> 1;
        S[OFF_W1 + hf * 6144 + k * 64 + h * 2 + gg] = v;
    }
    // L2: identity layout (lane reads cols (2l, 2l+1): lanes 0-7 i, 8-15 f, 16-23 g, 24-31 o)
    for (int idx = tid; idx < K2 * N2; idx += NTHREAD) {
        int k = idx >> 6, j = idx & (N2 - 1);
        S[OFF_W2 + idx] = (k < 32) ? W2[k * N2 + j] : U2[(k - 32) * N2 + j];
    }
    for (int j = tid; j < N0; j += NTHREAD) {
        int g = j >> 6, h = j & 63, hf = g & 1, gg = g >> 1, l = h >> 1, e = h & 1;
        S[OFF_B0 + hf * 128 + l * 4 + gg * 2 + e] = b0[j];
    }
    if (tid < N1) {
        int g = tid >> 5, h = tid & 31, hf = g & 1, gg = g >> 1;
        S[OFF_B1 + hf * 64 + h * 2 + gg] = b1[tid];
    }
    if (tid < N2) S[OFF_B2 + tid] = b2[tid];
    if (tid < 16) S[OFF_WD + tid] = Wd[tid];
    for (int i = tid; i < ROWS * (K0 + K1 + K2); i += NTHREAD) S[OFF_V0 + i] = 0.0f;
    __syncthreads();

    // ---- per-team row ownership ----
    const int rl0 = team * 4;
    const int grow0 = blockIdx.x * ROWS + rl0;
    float* v0b[4]; float* v1b[4]; float* v2b[4];
    const float* xp[4];
#pragma unroll
    for (int r = 0; r < 4; r++) {
        v0b[r] = S + OFF_V0 + (rl0 + r) * K0;
        v1b[r] = S + OFF_V1 + (rl0 + r) * K1;
        v2b[r] = S + OFF_V2 + (rl0 + r) * K2;
        xp[r] = x + (size_t)(grow0 + r) * (Tt * Ff) + 2 * lane;
    }
    float* scb = S + OFF_SC + team * 384;
    ull*   SCu = reinterpret_cast<ull*>(scb);     // 128 ull  (L0 u exchange)
    float* SCf = scb + 256;                       // 128 f    (L1 u exchange)

    // states: B (half 1) owns c0, c1; both warps own c2 for their 2 rows
    float c0x[4], c0y[4], c1[4], c2x[2], c2y[2];
#pragma unroll
    for (int r = 0; r < 4; r++) { c0x[r] = c0y[r] = 0.0f; c1[r] = 0.0f; }
    c2x[0] = c2x[1] = c2y[0] = c2y[1] = 0.0f;

    // prologue: A commits x_0, prefetches x_1
    float2 xr[4];
    if (half == 0) {
#pragma unroll
        for (int r = 0; r < 4; r++) {
            float2 a = *(const float2*)(xp[r]);
            *(float2*)(v0b[r] + 2 * lane) = a;
            xr[r] = *(const float2*)(xp[r] + Ff);
        }
    }
    team_bar(barid);

    const float* w0b = S + OFF_W0 + half * 16384 + lane * 4;
    const float* b0b = S + OFF_B0 + half * 128 + lane * 4;
    const float* w1b = S + OFF_W1 + half * 6144 + lane * 2;
    const float* b1b = S + OFF_B1 + half * 64 + lane * 2;
    const int ra = half * 2;   // this warp's L2 rows within the team

    for (int t = 0; t < Tt; t++) {
        // ================= layer 0 accumulate (both warps, half gates each) ==========
        ull aP[4], aQ[4];
        {
            longlong2 bb = *(const longlong2*)(b0b);
#pragma unroll
            for (int r = 0; r < 4; r++) { aP[r] = bb.x; aQ[r] = bb.y; }
        }
#pragma unroll 4
        for (int k4 = 0; k4 < 32; k4++) {
            float4 vv[4];
#pragma unroll
            for (int r = 0; r < 4; r++) vv[r] = *(const float4*)(v0b[r] + k4 * 4);
#pragma unroll
            for (int kk = 0; kk < 4; kk++) {
                longlong2 w = *(const longlong2*)(w0b + (k4 * 4 + kk) * 128);
#pragma unroll
                for (int r = 0; r < 4; r++) {
                    float vk = (kk == 0) ? vv[r].x : (kk == 1) ? vv[r].y : (kk == 2) ? vv[r].z : vv[r].w;
                    ull d = dup2(vk);
                    fma2(aP[r], d, w.x); fma2(aQ[r], d, w.y);
                }
            }
        }
        float2 fh[4], oh[4];
        if (half == 0) {
            // A: u = sig(i) * tanh(g), exchange to B
#pragma unroll
            for (int r = 0; r < 4; r++) {
                float2 zi = unpk(aP[r]), zg = unpk(aQ[r]);
                SCu[r * 32 + lane] = pk2(sigf(zi.x) * tanhf_(zg.x),
                                         sigf(zi.y) * tanhf_(zg.y));
            }
        } else {
            // B: f-hat, o-hat
#pragma unroll
            for (int r = 0; r < 4; r++) {
                float2 zf = unpk(aP[r]), zo = unpk(aQ[r]);
                fh[r].x = sigf(zf.x); fh[r].y = sigf(zf.y);
                oh[r].x = sigf(zo.x); oh[r].y = sigf(zo.y);
            }
        }
        team_bar(barid);
        if (half == 1) {
            // B: c0/h0 update, publish h0
#pragma unroll
            for (int r = 0; r < 4; r++) {
                float2 u = unpk(SCu[r * 32 + lane]);
                c0x[r] = fh[r].x * c0x[r] + u.x;
                c0y[r] = fh[r].y * c0y[r] + u.y;
                float2 h;
                h.x = oh[r].x * tanhf_(c0x[r]);
                h.y = oh[r].y * tanhf_(c0y[r]);
                *(float2*)(v0b[r] + 64 + 2 * lane) = h;
                *(float2*)(v1b[r] + 2 * lane) = h;
            }
        } else {
            // A (in parallel): commit x_{t+1}, prefetch x_{t+2}
            if (t + 1 < Tt) {
#pragma unroll
                for (int r = 0; r < 4; r++) *(float2*)(v0b[r] + 2 * lane) = xr[r];
            }
            if (t + 2 < Tt) {
#pragma unroll
                for (int r = 0; r < 4; r++) xr[r] = *(const float2*)(xp[r] + (t + 2) * Ff);
            }
        }
        team_bar(barid);

        // ================= layer 1 accumulate (both warps, half gates each) ==========
        ull a1[4];
        {
            ull b1v = *(const ull*)(b1b);
#pragma unroll
            for (int r = 0; r < 4; r++) a1[r] = b1v;
        }
#pragma unroll 4
        for (int k4 = 0; k4 < 24; k4++) {
            float4 vv[4];
#pragma unroll
            for (int r = 0; r < 4; r++) vv[r] = *(const float4*)(v1b[r] + k4 * 4);
#pragma unroll
            for (int kk = 0; kk < 4; kk++) {
                ull w = *(const ull*)(w1b + (k4 * 4 + kk) * 64);
#pragma unroll
                for (int r = 0; r < 4; r++) {
                    float vk = (kk == 0) ? vv[r].x : (kk == 1) ? vv[r].y : (kk == 2) ? vv[r].z : vv[r].w;
                    fma2(a1[r], dup2(vk), w);
                }
            }
        }
        float f1[4], o1[4];
        if (half == 0) {
            // A: acc = (i, g) -> u
#pragma unroll
            for (int r = 0; r < 4; r++) {
                float2 z = unpk(a1[r]);
                SCf[r * 32 + lane] = sigf(z.x) * tanhf_(z.y);
            }
        } else {
            // B: acc = (f, o)
#pragma unroll
            for (int r = 0; r < 4; r++) {
                float2 z = unpk(a1[r]);
                f1[r] = sigf(z.x); o1[r] = sigf(z.y);
            }
        }
        team_bar(barid);
        if (half == 1) {
#pragma unroll
            for (int r = 0; r < 4; r++) {
                float u = SCf[r * 32 + lane];
                c1[r] = f1[r] * c1[r] + u;
                float h = o1[r] * tanhf_(c1[r]);
                v1b[r][64 + lane] = h;
                v2b[r][lane] = h;
            }
        }
        team_bar(barid);

        // ================= layer 2 (row-split: 2 rows per warp, self-contained) ======
        ull q[2];
        {
            ull bq = *(const ull*)(S + OFF_B2 + 2 * lane);
            q[0] = bq; q[1] = bq;
        }
#pragma unroll 4
        for (int k4 = 0; k4 < 12; k4++) {
            float4 vv[2];
#pragma unroll
            for (int rr = 0; rr < 2; rr++) vv[rr] = *(const float4*)(v2b[ra + rr] + k4 * 4);
#pragma unroll
            for (int kk = 0; kk < 4; kk++) {
                ull w = *(const ull*)(S + OFF_W2 + (k4 * 4 + kk) * 64 + 2 * lane);
#pragma unroll
                for (int rr = 0; rr < 2; rr++) {
                    float vk = (kk == 0) ? vv[rr].x : (kk == 1) ? vv[rr].y : (kk == 2) ? vv[rr].z : vv[rr].w;
                    fma2(q[rr], dup2(vk), w);
                }
            }
        }
#pragma unroll
        for (int rr = 0; rr < 2; rr++) {
            float2 z = unpk(q[rr]);  // lanes 0-7: i pair, 8-15: f, 16-23: g, 24-31: o
            float fx = __shfl_down_sync(0xffffffffu, z.x, 8);
            float fy = __shfl_down_sync(0xffffffffu, z.y, 8);
            float gx = __shfl_down_sync(0xffffffffu, z.x, 16);
            float gy = __shfl_down_sync(0xffffffffu, z.y, 16);
            float ox = __shfl_down_sync(0xffffffffu, z.x, 24);
            float oy = __shfl_down_sync(0xffffffffu, z.y, 24);
            if (lane < 8) {
                c2x[rr] = sigf(fx) * c2x[rr] + sigf(z.x) * tanhf_(gx);
                c2y[rr] = sigf(fy) * c2y[rr] + sigf(z.y) * tanhf_(gy);
                float2 h;
                h.x = sigf(ox) * tanhf_(c2x[rr]);
                h.y = sigf(oy) * tanhf_(c2y[rr]);
                *(float2*)(v2b[ra + rr] + 32 + 2 * lane) = h;
            }
        }
        __syncwarp();
    }

    // ================= dense head (each warp: its 2 L2 rows) =================
    const float bdv = bd[0];
#pragma unroll
    for (int rr = 0; rr < 2; rr++) {
        float p = (lane < 16) ? v2b[ra + rr][32 + lane] * S[OFF_WD + lane] : 0.0f;
#pragma unroll
        for (int off = 8; off > 0; off >>= 1) p += __shfl_down_sync(0xffffffffu, p, off);
        if (lane == 0) out[grow0 + ra + rr] = p + bdv;
    }
}

extern "C" void kernel_launch(void* const* d_in, const int* in_sizes, int n_in,
                              void* d_out, int out_size) {
    cudaFuncSetAttribute(stacked_lstm_kernel,
                         cudaFuncAttributeMaxDynamicSharedMemorySize, (int)SMEM_BYTES);
    stacked_lstm_kernel<<<Bb / ROWS, NTHREAD, SMEM_BYTES>>>(
        (const float*)d_in[0],
        (const float*)d_in[1], (const float*)d_in[2], (const float*)d_in[3],
        (const float*)d_in[4], (const float*)d_in[5], (const float*)d_in[6],
        (const float*)d_in[7], (const float*)d_in[8], (const float*)d_in[9],
        (const float*)d_in[10], (const float*)d_in[11],
        (float*)d_out);
}

// round 7
// speedup vs baseline: 1.1725x; 1.1725x over previous
#include <cuda_runtime.h>

// ---------------- problem constants ----------------
#define NTHREAD 256
#define ROWS 16              // rows per CTA; warps 0-3: L0, warps 4-7: L1+L2 (same rows)
static constexpr int Bb = 2048, Tt = 256, Ff = 64;
static constexpr int K0 = 128, N0 = 256;
static constexpr int K1 = 96,  N1 = 128;
static constexpr int K2 = 48,  N2 = 64;

// ---------------- shared memory layout (float offsets) ----------------
static constexpr int OFF_W0 = 0;                     // perm0, row stride 256
static constexpr int OFF_W1 = OFF_W0 + K0 * N0;      // 32768 perm1, row stride 128
static constexpr int OFF_W2 = OFF_W1 + K1 * N1;      // 45056 identity, row stride 64
static constexpr int OFF_B0 = OFF_W2 + K2 * N2;      // 48128
static constexpr int OFF_B1 = OFF_B0 + N0;           // 48384
static constexpr int OFF_B2 = OFF_B1 + N1;           // 48512
static constexpr int OFF_WD = OFF_B2 + N2;           // 48576
static constexpr int OFF_X  = OFF_WD + 16;           // 48592  x staging [16][64]
static constexpr int OFF_H0 = OFF_X + ROWS * 64;     // 49616  h0 double buf [2][16][64]
static constexpr int OFF_H1 = OFF_H0 + 2 * ROWS * 64;// 51664  h1 [16][32]
static constexpr int OFF_H2 = OFF_H1 + ROWS * 32;    // 52176  h2 [16][16]
static constexpr int SMEM_FLOATS = OFF_H2 + ROWS * 16;  // 52432
static constexpr size_t SMEM_BYTES = (size_t)SMEM_FLOATS * sizeof(float); // 209728 B

typedef unsigned long long ull;

// ---------------- packed f32x2 helpers ----------------
__device__ __forceinline__ void fma2(ull& acc, ull a, ull b) {
    asm("fma.rn.f32x2 %0, %1, %2, %0;" : "+l"(acc) : "l"(a), "l"(b));
}
__device__ __forceinline__ ull dup2(float v) {
    ull u; asm("mov.b64 %0, {%1, %1};" : "=l"(u) : "f"(v)); return u;
}
__device__ __forceinline__ float2 unpk(ull u) {
    float2 r; asm("mov.b64 {%0, %1}, %2;" : "=f"(r.x), "=f"(r.y) : "l"(u)); return r;
}
__device__ __forceinline__ float sigf(float x) {
    return __fdividef(1.0f, 1.0f + __expf(-x));
}
__device__ __forceinline__ float tanhf_(float x) {
    float e = __expf(-2.0f * x);
    return __fdividef(2.0f, 1.0f + e) - 1.0f;
}

// column permutations (as round 2)
__device__ __forceinline__ int perm0(int j) {
    int jp = j >> 1, e = j & 1, rp = jp >> 5, l = jp & 31, g = rp >> 1, s = rp & 1;
    return g * 128 + l * 4 + s * 2 + e;
}
__device__ __forceinline__ int perm1(int j) {
    int jp = j >> 1, e = j & 1, rp = jp >> 5, l = jp & 31;
    return l * 4 + rp * 2 + e;
}

__global__ void __launch_bounds__(NTHREAD, 1)
stacked_lstm_kernel(const float* __restrict__ x,
                    const float* __restrict__ W0, const float* __restrict__ U0, const float* __restrict__ b0,
                    const float* __restrict__ W1, const float* __restrict__ U1, const float* __restrict__ b1,
                    const float* __restrict__ W2, const float* __restrict__ U2, const float* __restrict__ b2,
                    const float* __restrict__ Wd, const float* __restrict__ bd,
                    float* __restrict__ out) {
    extern __shared__ float S[];
    const int tid = threadIdx.x, lane = tid & 31, warp = tid >> 5;

    // ---- stage weights (permuted) ----
    for (int idx = tid; idx < K0 * N0; idx += NTHREAD) {
        int k = idx >> 8, j = idx & (N0 - 1);
        float v = (k < 64) ? W0[k * N0 + j] : U0[(k - 64) * N0 + j];
        S[OFF_W0 + k * N0 + perm0(j)] = v;
    }
    for (int idx = tid; idx < K1 * N1; idx += NTHREAD) {
        int k = idx >> 7, j = idx & (N1 - 1);
        float v = (k < 64) ? W1[k * N1 + j] : U1[(k - 64) * N1 + j];
        S[OFF_W1 + k * N1 + perm1(j)] = v;
    }
    for (int idx = tid; idx < K2 * N2; idx += NTHREAD) {
        int k = idx >> 6, j = idx & (N2 - 1);
        S[OFF_W2 + idx] = (k < 32) ? W2[k * N2 + j] : U2[(k - 32) * N2 + j];
    }
    for (int j = tid; j < N0; j += NTHREAD) S[OFF_B0 + perm0(j)] = b0[j];
    if (tid < N1) S[OFF_B1 + perm1(tid)] = b1[tid];
    if (tid < N2) S[OFF_B2 + tid] = b2[tid];
    if (tid < 16) S[OFF_WD + tid] = Wd[tid];
    // zero h states (h0 both buffers, h1, h2)
    for (int i = tid; i < 2 * ROWS * 64 + ROWS * 32 + ROWS * 16; i += NTHREAD)
        S[OFF_H0 + i] = 0.0f;
    __syncthreads();

    const int rb = (warp & 3) * 4;               // this warp's 4 rows (both roles)
    const int grow0 = blockIdx.x * ROWS + rb;
    const bool isL0 = (warp < 4);

    // per-role persistent state
    float c0x[4], c0y[4], c1x[4], c1y[4], c2x[4], c2y[4];
#pragma unroll
    for (int r = 0; r < 4; r++)
        c0x[r] = c0y[r] = c1x[r] = c1y[r] = c2x[r] = c2y[r] = 0.0f;

    const float* xp[4];
#pragma unroll
    for (int r = 0; r < 4; r++)
        xp[r] = x + (size_t)(grow0 + r) * (Tt * Ff) + 2 * lane;

    // hoisted biases
    longlong2 bA, bB, bb1; ull bq;
    if (isL0) {
        bA = *(const longlong2*)(S + OFF_B0 + lane * 4);
        bB = *(const longlong2*)(S + OFF_B0 + 128 + lane * 4);
    } else {
        bb1 = *(const longlong2*)(S + OFF_B1 + lane * 4);
        bq = *(const ull*)(S + OFF_B2 + 2 * lane);
    }

    // prologue: L0 warps commit x(0), prefetch x(1)
    float2 xr[4];
    if (isL0) {
#pragma unroll
        for (int r = 0; r < 4; r++) {
            float2 a = *(const float2*)(xp[r]);
            *(float2*)(S + OFF_X + (rb + r) * 64 + 2 * lane) = a;
            xr[r] = *(const float2*)(xp[r] + Ff);
        }
    }
    __syncthreads();

    for (int k = 0; k < Tt + 2; k++) {
        if (isL0) {
            if (k < Tt) {
                // =================== layer 0, t = k ===================
                ull a0[4], a1[4], a2[4], a3[4];
#pragma unroll
                for (int r = 0; r < 4; r++) { a0[r] = bA.x; a1[r] = bA.y; a2[r] = bB.x; a3[r] = bB.y; }
                const float* xb = S + OFF_X + rb * 64;
                const float* hb = S + OFF_H0 + ((k + 1) & 1) * (ROWS * 64) + rb * 64;
                // x half: k-rows 0..63
#pragma unroll 4
                for (int k4 = 0; k4 < 16; k4++) {
                    float4 vv[4];
#pragma unroll
                    for (int r = 0; r < 4; r++) vv[r] = *(const float4*)(xb + r * 64 + k4 * 4);
#pragma unroll
                    for (int kk = 0; kk < 4; kk++) {
                        const float* wr = S + OFF_W0 + (k4 * 4 + kk) * N0 + lane * 4;
                        longlong2 wA = *(const longlong2*)(wr);
                        longlong2 wB = *(const longlong2*)(wr + 128);
#pragma unroll
                        for (int r = 0; r < 4; r++) {
                            float vk = (kk == 0) ? vv[r].x : (kk == 1) ? vv[r].y : (kk == 2) ? vv[r].z : vv[r].w;
                            ull d = dup2(vk);
                            fma2(a0[r], d, wA.x); fma2(a1[r], d, wA.y);
                            fma2(a2[r], d, wB.x); fma2(a3[r], d, wB.y);
                        }
                    }
                }
                // h half: k-rows 64..127 (h0(k-1) from double buffer)
#pragma unroll 4
                for (int k4 = 0; k4 < 16; k4++) {
                    float4 vv[4];
#pragma unroll
                    for (int r = 0; r < 4; r++) vv[r] = *(const float4*)(hb + r * 64 + k4 * 4);
#pragma unroll
                    for (int kk = 0; kk < 4; kk++) {
                        const float* wr = S + OFF_W0 + (64 + k4 * 4 + kk) * N0 + lane * 4;
                        longlong2 wA = *(const longlong2*)(wr);
                        longlong2 wB = *(const longlong2*)(wr + 128);
#pragma unroll
                        for (int r = 0; r < 4; r++) {
                            float vk = (kk == 0) ? vv[r].x : (kk == 1) ? vv[r].y : (kk == 2) ? vv[r].z : vv[r].w;
                            ull d = dup2(vk);
                            fma2(a0[r], d, wA.x); fma2(a1[r], d, wA.y);
                            fma2(a2[r], d, wB.x); fma2(a3[r], d, wB.y);
                        }
                    }
                }
                // finalize -> h0(k) into buffer k&1
                float* hout = S + OFF_H0 + (k & 1) * (ROWS * 64) + rb * 64;
#pragma unroll
                for (int r = 0; r < 4; r++) {
                    float2 zi = unpk(a0[r]), zf = unpk(a1[r]), zg = unpk(a2[r]), zo = unpk(a3[r]);
                    c0x[r] = sigf(zf.x) * c0x[r] + sigf(zi.x) * tanhf_(zg.x);
                    c0y[r] = sigf(zf.y) * c0y[r] + sigf(zi.y) * tanhf_(zg.y);
                    float2 h;
                    h.x = sigf(zo.x) * tanhf_(c0x[r]);
                    h.y = sigf(zo.y) * tanhf_(c0y[r]);
                    *(float2*)(hout + r * 64 + 2 * lane) = h;
                }
                // commit x(k+1), prefetch x(k+2)
                if (k + 1 < Tt) {
#pragma unroll
                    for (int r = 0; r < 4; r++)
                        *(float2*)(S + OFF_X + (rb + r) * 64 + 2 * lane) = xr[r];
                }
                if (k + 2 < Tt) {
#pragma unroll
                    for (int r = 0; r < 4; r++)
                        xr[r] = *(const float2*)(xp[r] + (size_t)(k + 2) * Ff);
                }
            }
        } else {
            // =================== layer 2, t = k-2 (before L1 overwrites h1) ===========
            if (k >= 2) {
                ull q[4];
#pragma unroll
                for (int r = 0; r < 4; r++) q[r] = bq;
                const float* h1b = S + OFF_H1 + rb * 32;
                const float* h2b = S + OFF_H2 + rb * 16;
#pragma unroll 4
                for (int k4 = 0; k4 < 8; k4++) {
                    float4 vv[4];
#pragma unroll
                    for (int r = 0; r < 4; r++) vv[r] = *(const float4*)(h1b + r * 32 + k4 * 4);
#pragma unroll
                    for (int kk = 0; kk < 4; kk++) {
                        ull w = *(const ull*)(S + OFF_W2 + (k4 * 4 + kk) * N2 + 2 * lane);
#pragma unroll
                        for (int r = 0; r < 4; r++) {
                            float vk = (kk == 0) ? vv[r].x : (kk == 1) ? vv[r].y : (kk == 2) ? vv[r].z : vv[r].w;
                            fma2(q[r], dup2(vk), w);
                        }
                    }
                }
#pragma unroll 4
                for (int k4 = 0; k4 < 4; k4++) {
                    float4 vv[4];
#pragma unroll
                    for (int r = 0; r < 4; r++) vv[r] = *(const float4*)(h2b + r * 16 + k4 * 4);
#pragma unroll
                    for (int kk = 0; kk < 4; kk++) {
                        ull w = *(const ull*)(S + OFF_W2 + (32 + k4 * 4 + kk) * N2 + 2 * lane);
#pragma unroll
                        for (int r = 0; r < 4; r++) {
                            float vk = (kk == 0) ? vv[r].x : (kk == 1) ? vv[r].y : (kk == 2) ? vv[r].z : vv[r].w;
                            fma2(q[r], dup2(vk), w);
                        }
                    }
                }
#pragma unroll
                for (int r = 0; r < 4; r++) {
                    float2 z = unpk(q[r]);  // lanes 0-7: i, 8-15: f, 16-23: g, 24-31: o
                    float fx = __shfl_down_sync(0xffffffffu, z.x, 8);
                    float fy = __shfl_down_sync(0xffffffffu, z.y, 8);
                    float gx = __shfl_down_sync(0xffffffffu, z.x, 16);
                    float gy = __shfl_down_sync(0xffffffffu, z.y, 16);
                    float ox = __shfl_down_sync(0xffffffffu, z.x, 24);
                    float oy = __shfl_down_sync(0xffffffffu, z.y, 24);
                    if (lane < 8) {
                        c2x[r] = sigf(fx) * c2x[r] + sigf(z.x) * tanhf_(gx);
                        c2y[r] = sigf(fy) * c2y[r] + sigf(z.y) * tanhf_(gy);
                        float2 h;
                        h.x = sigf(ox) * tanhf_(c2x[r]);
                        h.y = sigf(oy) * tanhf_(c2y[r]);
                        *(float2*)(S + OFF_H2 + (rb + r) * 16 + 2 * lane) = h;
                    }
                }
            }
            // =================== layer 1, t = k-1 ===================
            if (k >= 1 && k < Tt + 1) {
                ull p0[4], p1[4];
#pragma unroll
                for (int r = 0; r < 4; r++) { p0[r] = bb1.x; p1[r] = bb1.y; }
                const float* h0b = S + OFF_H0 + ((k - 1) & 1) * (ROWS * 64) + rb * 64;
                const float* h1b = S + OFF_H1 + rb * 32;
#pragma unroll 4
                for (int k4 = 0; k4 < 16; k4++) {
                    float4 vv[4];
#pragma unroll
                    for (int r = 0; r < 4; r++) vv[r] = *(const float4*)(h0b + r * 64 + k4 * 4);
#pragma unroll
                    for (int kk = 0; kk < 4; kk++) {
                        longlong2 w = *(const longlong2*)(S + OFF_W1 + (k4 * 4 + kk) * N1 + lane * 4);
#pragma unroll
                        for (int r = 0; r < 4; r++) {
                            float vk = (kk == 0) ? vv[r].x : (kk == 1) ? vv[r].y : (kk == 2) ? vv[r].z : vv[r].w;
                            ull d = dup2(vk);
                            fma2(p0[r], d, w.x); fma2(p1[r], d, w.y);
                        }
                    }
                }
#pragma unroll 4
                for (int k4 = 0; k4 < 8; k4++) {
                    float4 vv[4];
#pragma unroll
                    for (int r = 0; r < 4; r++) vv[r] = *(const float4*)(h1b + r * 32 + k4 * 4);
#pragma unroll
                    for (int kk = 0; kk < 4; kk++) {
                        longlong2 w = *(const longlong2*)(S + OFF_W1 + (64 + k4 * 4 + kk) * N1 + lane * 4);
#pragma unroll
                        for (int r = 0; r < 4; r++) {
                            float vk = (kk == 0) ? vv[r].x : (kk == 1) ? vv[r].y : (kk == 2) ? vv[r].z : vv[r].w;
                            ull d = dup2(vk);
                            fma2(p0[r], d, w.x); fma2(p1[r], d, w.y);
                        }
                    }
                }
#pragma unroll
                for (int r = 0; r < 4; r++) {
                    float2 zA = unpk(p0[r]), zB = unpk(p1[r]);  // <16: (i,g); >=16: (f,o)
                    float fx = __shfl_down_sync(0xffffffffu, zA.x, 16);
                    float fy = __shfl_down_sync(0xffffffffu, zA.y, 16);
                    float ox = __shfl_down_sync(0xffffffffu, zB.x, 16);
                    float oy = __shfl_down_sync(0xffffffffu, zB.y, 16);
                    if (lane < 16) {
                        c1x[r] = sigf(fx) * c1x[r] + sigf(zA.x) * tanhf_(zB.x);
                        c1y[r] = sigf(fy) * c1y[r] + sigf(zA.y) * tanhf_(zB.y);
                        float2 h;
                        h.x = sigf(ox) * tanhf_(c1x[r]);
                        h.y = sigf(oy) * tanhf_(c1y[r]);
                        *(float2*)(S + OFF_H1 + (rb + r) * 32 + 2 * lane) = h;
                    }
                }
            }
        }
        __syncthreads();
    }

    // ================= dense head (partner warps, their 4 rows) =================
    if (!isL0) {
        const float bdv = bd[0];
#pragma unroll
        for (int r = 0; r < 4; r++) {
            float p = (lane < 16) ? S[OFF_H2 + (rb + r) * 16 + lane] * S[OFF_WD + lane] : 0.0f;
#pragma unroll
            for (int off = 8; off > 0; off >>= 1) p += __shfl_down_sync(0xffffffffu, p, off);
            if (lane == 0) out[grow0 + r] = p + bdv;
        }
    }
}

extern "C" void kernel_launch(void* const* d_in, const int* in_sizes, int n_in,
                              void* d_out, int out_size) {
    cudaFuncSetAttribute(stacked_lstm_kernel,
                         cudaFuncAttributeMaxDynamicSharedMemorySize, (int)SMEM_BYTES);
    stacked_lstm_kernel<<<Bb / ROWS, NTHREAD, SMEM_BYTES>>>(
        (const float*)d_in[0],
        (const float*)d_in[1], (const float*)d_in[2], (const float*)d_in[3],
        (const float*)d_in[4], (const float*)d_in[5], (const float*)d_in[6],
        (const float*)d_in[7], (const float*)d_in[8], (const float*)d_in[9],
        (const float*)d_in[10], (const float*)d_in[11],
        (float*)d_out);
}